// round 12
// baseline (speedup 1.0000x reference)
#include <cuda_runtime.h>
#include <cstdint>

typedef unsigned long long ull;

#define NF 5
#define NK 6
#define NT 12
#define NR 16
#define NM 3600
#define NS 400
#define NSH 200            // 2 scenes per thread: (s, s+200)
#define NB 128
#define NSPLIT 118         // 5*118 = 590 blocks = 2 clean waves of 296
#define MPW_MAX 31
#define NROW 5760          // Rx*F*72
#define NRFK 480           // Rx*F*6
#define MICCH 8
#define CH   (NS / MICCH)  // 50

// staged chunk (fixed max layout): per m 12 float4
#define NF4_TOT  (MPW_MAX * 12)          // 372

// merged setup kernel block ranges (256 threads each)
#define MB_META 15
#define MB_C1   141
#define MB_C2   282

// out1 grid: mic partial blocks FIRST, then grid-stride repA blocks
#define MICP_BLOCKS (NR * NF * MICCH)   // 640
#define REPA_ITEMS  (NROW * 100)        // 576000 float4-pairs
#define REPA_BLOCKS 563                  // ceil(576000 / (256*4))
#define REPA_STRIDE (REPA_BLOCKS * 256)  // 144128

#define TWO_PI_D     6.283185307179586
#define INV2PI_F     0.15915494309189535f
#define PI2_HI_F     6.2831854820251465f
#define PI2_LO_F    -1.7484555e-7f
#define PI_F         3.14159265358979f
#define THETA_HI     0.3490658503988659f   // 20*pi/180

// ---------------- scratch (device globals; no allocation) ----------------
__device__ __align__(16) float g_C1f[NF * NM * 12];   // per (f,m): cr0..5, ci0..5
__device__ __align__(16) float g_C2f[NF * NM * 32];   // per (f,m): cr0..15, ci0..15
__device__ __align__(16) float4 g_meta4[NM];
__device__ __align__(16) float2 g_A2p[NSPLIT * NF * NK * NS];
__device__ __align__(16) float2 g_Gp [NSPLIT * NF * NR * NS];
__device__ __align__(16) float2 g_A2[NF * NK * NS];
__device__ __align__(16) float2 g_G [NF * NR * NS];
__device__ float2 g_micp[MICCH * NRFK * NB];

// ---------------- packed f32x2 helpers ----------------
__device__ __forceinline__ ull pk(float x, float y) {
    ull r; asm("mov.b64 %0, {%1, %2};" : "=l"(r) : "f"(x), "f"(y)); return r;
}
__device__ __forceinline__ float2 upk(ull v) {
    float x, y; asm("mov.b64 {%0, %1}, %2;" : "=f"(x), "=f"(y) : "l"(v));
    return make_float2(x, y);
}
__device__ __forceinline__ ull fma2(ull a, ull b, ull c) {
    ull d; asm("fma.rn.f32x2 %0, %1, %2, %3;" : "=l"(d) : "l"(a), "l"(b), "l"(c));
    return d;
}

// ---- fp32 angle reduction ----
__device__ __forceinline__ float reduce_ang(float kd_hi, float d) {
    float p = kd_hi * d;
    float n = rintf(p * INV2PI_F);
    float r1 = fmaf(-n, PI2_HI_F, p);
    r1 = fmaf(-n, PI2_LO_F, r1);
    return r1;
}

__device__ __forceinline__ void cexp_parts(float kd_hi, float d, float& a1, float& a2) {
    float amp = __fdividef(1e-3f, d * d);
    float sn, cs;
    __sincosf(reduce_ang(kd_hi, d), &sn, &cs);
    a1 = amp * cs; a2 = amp * sn;     // h = a1 - i*a2
}

__device__ __forceinline__ void cmac_s(float& ar, float& ai, float cr, float ci,
                                       float hr, float hi) {
    ar = fmaf(cr, hr, ar); ar = fmaf(-ci, hi, ar);
    ai = fmaf(cr, hi, ai); ai = fmaf(ci, hr, ai);
}

__device__ __forceinline__ float2 meta_phase(const float* theta_in, int m) {
    float th = theta_in[m];
    th = fminf(fmaxf(th, -PI_F), THETA_HI);
    float ps, pc; __sincosf(th, &ps, &pc);
    return make_float2(pc, ps);
}

// ---------------- kernel 1: merged setup (meta | C1 | C2) ----------------
__global__ void k_setup(const float* __restrict__ w,   const float* __restrict__ theta_in,
                        const float* __restrict__ fv,  const float* __restrict__ txp,
                        const float* __restrict__ rxp, const float* __restrict__ metap) {
    __shared__ float2 spri[NF * NK * NT];
    __shared__ float  sant[NR * 3];
    __shared__ float  sf[NF];
    int bx = blockIdx.x;
    int tid = threadIdx.x;

    if (bx < MB_META) {
        int m = bx * 256 + tid;
        if (m < NM)
            g_meta4[m] = make_float4(metap[3 * m + 0], metap[3 * m + 1], metap[3 * m + 2], 0.f);
        return;
    }

    if (bx < MB_META + MB_C1) {
        // ---- C1: 2 threads per (f,m), 3 k's each ----
        if (tid < NT * 3) sant[tid] = txp[tid];
        if (tid >= 64 && tid < 64 + NF) sf[tid - 64] = fv[tid - 64];
        for (int i = tid; i < NF * NK * NT; i += 256) {
            float s, c; sincosf(w[i], &s, &c);
            spri[i] = make_float2(c, s);
        }
        __syncthreads();

        int t = (bx - MB_META) * 256 + tid;
        if (t >= NF * NM * 2) return;
        int half = t & 1;
        int g = t >> 1;
        int fi = g / NM;
        int m  = g - fi * NM;

        float2 ph = meta_phase(theta_in, m);
        float mx = metap[3 * m + 0], my = metap[3 * m + 1], mz = metap[3 * m + 2];
        float kd_hi = (float)(TWO_PI_D * (double)sf[fi] / 3.0e8);

        float h1r[NT], h1i[NT];
        #pragma unroll
        for (int tx = 0; tx < NT; tx++) {
            float dx = sant[3 * tx + 0] - mx, dy = sant[3 * tx + 1] - my, dz = sant[3 * tx + 2] - mz;
            float d = sqrtf(dx * dx + dy * dy + dz * dz);
            float a1, a2; cexp_parts(kd_hi, d, a1, a2);
            h1r[tx] = a1; h1i[tx] = -a2;
        }
        float* dst = g_C1f + ((size_t)fi * NM + m) * 12;
        #pragma unroll
        for (int kk = 0; kk < 3; kk++) {
            int k = half * 3 + kk;
            float ar = 0.f, ai = 0.f;
            #pragma unroll
            for (int tx = 0; tx < NT; tx++) {
                float2 p = spri[(fi * NK + k) * NT + tx];
                cmac_s(ar, ai, p.x, p.y, h1r[tx], h1i[tx]);
            }
            dst[k]     = ar * ph.x - ai * ph.y;
            dst[6 + k] = ar * ph.y + ai * ph.x;
        }
        return;
    }

    // ---- C2: 4 threads per (f,m), 4 r's each ----
    if (tid < NR * 3) sant[tid] = rxp[tid];
    if (tid >= 64 && tid < 64 + NF) sf[tid - 64] = fv[tid - 64];
    __syncthreads();

    int t = (bx - MB_META - MB_C1) * 256 + tid;
    if (t >= NF * NM * 4) return;
    int rq = t & 3;
    int g = t >> 2;
    int fi = g / NM;
    int m  = g - fi * NM;

    float2 ph = meta_phase(theta_in, m);
    float mx = metap[3 * m + 0], my = metap[3 * m + 1], mz = metap[3 * m + 2];
    float kd_hi = (float)(TWO_PI_D * (double)sf[fi] / 3.0e8);

    float cr[4], ci[4];
    int r0 = rq * 4;
    #pragma unroll
    for (int j = 0; j < 4; j++) {
        int r = r0 + j;
        float dx = sant[3 * r + 0] - mx, dy = sant[3 * r + 1] - my, dz = sant[3 * r + 2] - mz;
        float d = sqrtf(dx * dx + dy * dy + dz * dz);
        float a1, a2; cexp_parts(kd_hi, d, a1, a2);
        float hr = a1, hi = -a2;
        cr[j] = ph.x * hr - ph.y * hi;
        ci[j] = ph.x * hi + ph.y * hr;
    }
    float* dst = g_C2f + ((size_t)fi * NM + m) * 32;
    ((float4*)dst)[rq]        = make_float4(cr[0], cr[1], cr[2], cr[3]);
    ((float4*)(dst + 16))[rq] = make_float4(ci[0], ci[1], ci[2], ci[3]);
}

// ---------------- kernel 2: fused A2 + G (590 blocks = 2 clean waves) ----
__global__ void __launch_bounds__(224, 2) k_main(const float* __restrict__ scenep,
                                                 const float* __restrict__ fv) {
    __shared__ __align__(16) float4 sbuf[NF4_TOT];

    int tid = threadIdx.x;
    int item = blockIdx.x;               // 0..589
    int f  = item / NSPLIT;
    int ms = item - f * NSPLIT;
    int m0 = (ms * NM) / NSPLIT;
    int m1 = ((ms + 1) * NM) / NSPLIT;
    int cnt = m1 - m0;                   // 30 or 31
    int c2base = cnt * 3;
    int metabase = cnt * 11;
    int tot = cnt * 12;

    {
        const float4* c1g = (const float4*)g_C1f + (size_t)f * NM * 3 + (size_t)m0 * 3;
        const float4* c2g = (const float4*)g_C2f + (size_t)f * NM * 8 + (size_t)m0 * 8;
        const float4* mg  = g_meta4 + m0;
        for (int j = tid; j < tot; j += 224) {
            const float4* src;
            if (j < c2base)        src = c1g + j;
            else if (j < metabase) src = c2g + (j - c2base);
            else                   src = mg  + (j - metabase);
            unsigned sa32 = (unsigned)__cvta_generic_to_shared(&sbuf[j]);
            asm volatile("cp.async.cg.shared.global [%0], [%1], 16;"
                         :: "r"(sa32), "l"(src) : "memory");
        }
        asm volatile("cp.async.commit_group;" ::: "memory");
    }

    bool valid = (tid < NSH);
    int sa = valid ? tid : 0;
    int sb = sa + NSH;
    float sx1 = scenep[3 * sa + 0], sy1 = scenep[3 * sa + 1], sz1 = scenep[3 * sa + 2];
    float sx2 = scenep[3 * sb + 0], sy2 = scenep[3 * sb + 1], sz2 = scenep[3 * sb + 2];

    float kd_hi = (float)(TWO_PI_D * (double)__ldg(&fv[f]) / 3.0e8);

    ull aRa[3], aIa[3], gRa[8], gIa[8];
    ull aRb[3], aIb[3], gRb[8], gIb[8];
    #pragma unroll
    for (int i = 0; i < 3; i++) { aRa[i]=0ull; aIa[i]=0ull; aRb[i]=0ull; aIb[i]=0ull; }
    #pragma unroll
    for (int i = 0; i < 8; i++) { gRa[i]=0ull; gIa[i]=0ull; gRb[i]=0ull; gIb[i]=0ull; }

    asm volatile("cp.async.wait_group 0;" ::: "memory");
    __syncthreads();

    #pragma unroll 3
    for (int m = 0; m < cnt; ++m) {
        float4 mp = sbuf[metabase + m];

        float dx1 = mp.x - sx1, dy1 = mp.y - sy1, dz1 = mp.z - sz1;
        float d2a = fmaf(dx1, dx1, fmaf(dy1, dy1, dz1 * dz1));
        float rsa = rsqrtf(d2a);
        float da  = d2a * rsa;
        float ampa = 1e-3f * rsa * rsa;
        float sna, csa;
        __sincosf(reduce_ang(kd_hi, da), &sna, &csa);
        float hxa = ampa * csa, hya = -ampa * sna;
        ull hx2a  = pk(hxa, hxa);
        ull hy2a  = pk(hya, hya);
        ull hyn2a = pk(-hya, -hya);

        float dx2 = mp.x - sx2, dy2 = mp.y - sy2, dz2 = mp.z - sz2;
        float d2b = fmaf(dx2, dx2, fmaf(dy2, dy2, dz2 * dz2));
        float rsb = rsqrtf(d2b);
        float db  = d2b * rsb;
        float ampb = 1e-3f * rsb * rsb;
        float snb, csb;
        __sincosf(reduce_ang(kd_hi, db), &snb, &csb);
        float hxb = ampb * csb, hyb = -ampb * snb;
        ull hx2b  = pk(hxb, hxb);
        ull hy2b  = pk(hyb, hyb);
        ull hyn2b = pk(-hyb, -hyb);

        #define PMAC2(Ra, Ia, Rb, Ib, CR, CI)                  \
            Ra = fma2(CR, hx2a, Ra); Ra = fma2(CI, hyn2a, Ra); \
            Ia = fma2(CR, hy2a, Ia); Ia = fma2(CI, hx2a, Ia);  \
            Rb = fma2(CR, hx2b, Rb); Rb = fma2(CI, hyn2b, Rb); \
            Ib = fma2(CR, hy2b, Ib); Ib = fma2(CI, hx2b, Ib);

        {
            const ulonglong2* c1s = (const ulonglong2*)&sbuf[m * 3];
            ulonglong2 u0 = c1s[0];
            ulonglong2 u1 = c1s[1];
            ulonglong2 u2 = c1s[2];
            PMAC2(aRa[0], aIa[0], aRb[0], aIb[0], u0.x, u1.y)
            PMAC2(aRa[1], aIa[1], aRb[1], aIb[1], u0.y, u2.x)
            PMAC2(aRa[2], aIa[2], aRb[2], aIb[2], u1.x, u2.y)
        }
        {
            const ulonglong2* c2s = (const ulonglong2*)&sbuf[c2base + m * 8];
            ulonglong2 v0 = c2s[0];
            ulonglong2 v1 = c2s[1];
            ulonglong2 v2 = c2s[2];
            ulonglong2 v3 = c2s[3];
            ulonglong2 w0 = c2s[4];
            ulonglong2 w1 = c2s[5];
            ulonglong2 w2 = c2s[6];
            ulonglong2 w3 = c2s[7];
            PMAC2(gRa[0], gIa[0], gRb[0], gIb[0], v0.x, w0.x)
            PMAC2(gRa[1], gIa[1], gRb[1], gIb[1], v0.y, w0.y)
            PMAC2(gRa[2], gIa[2], gRb[2], gIb[2], v1.x, w1.x)
            PMAC2(gRa[3], gIa[3], gRb[3], gIb[3], v1.y, w1.y)
            PMAC2(gRa[4], gIa[4], gRb[4], gIb[4], v2.x, w2.x)
            PMAC2(gRa[5], gIa[5], gRb[5], gIb[5], v2.y, w2.y)
            PMAC2(gRa[6], gIa[6], gRb[6], gIb[6], v3.x, w3.x)
            PMAC2(gRa[7], gIa[7], gRb[7], gIb[7], v3.y, w3.y)
        }
        #undef PMAC2
    }

    if (valid) {
        float2* A2p = g_A2p + (size_t)ms * (NF * NK * NS);
        #pragma unroll
        for (int j = 0; j < 3; j++) {
            float2 r1 = upk(aRa[j]), i1 = upk(aIa[j]);
            float2 r2 = upk(aRb[j]), i2 = upk(aIb[j]);
            A2p[(f * NK + 2 * j)     * NS + sa] = make_float2(r1.x, i1.x);
            A2p[(f * NK + 2 * j + 1) * NS + sa] = make_float2(r1.y, i1.y);
            A2p[(f * NK + 2 * j)     * NS + sb] = make_float2(r2.x, i2.x);
            A2p[(f * NK + 2 * j + 1) * NS + sb] = make_float2(r2.y, i2.y);
        }
        float2* Gp = g_Gp + (size_t)ms * (NF * NR * NS);
        #pragma unroll
        for (int j = 0; j < 8; j++) {
            float2 r1 = upk(gRa[j]), i1 = upk(gIa[j]);
            float2 r2 = upk(gRb[j]), i2 = upk(gIb[j]);
            Gp[(f * NR + 2 * j)     * NS + sa] = make_float2(r1.x, i1.x);
            Gp[(f * NR + 2 * j + 1) * NS + sa] = make_float2(r1.y, i1.y);
            Gp[(f * NR + 2 * j)     * NS + sb] = make_float2(r2.x, i2.x);
            Gp[(f * NR + 2 * j + 1) * NS + sb] = make_float2(r2.y, i2.y);
        }
    }
}

// ---------------- kernel 3: reduce partials (128 thr, 172 blocks) --------
__global__ void __launch_bounds__(128) k_reduce() {
    int i = blockIdx.x * 128 + threadIdx.x;
    const float4* Ap = (const float4*)g_A2p;
    const float4* Gp = (const float4*)g_Gp;
    if (i < 6000) {                       // NF*NK*NS/2
        float4 acc = make_float4(0.f, 0.f, 0.f, 0.f);
        #pragma unroll 8
        for (int j = 0; j < NSPLIT; j++) {
            float4 p = Ap[(size_t)j * 6000 + i];
            acc.x += p.x; acc.y += p.y; acc.z += p.z; acc.w += p.w;
        }
        ((float4*)g_A2)[i] = acc;
    } else if (i < 22000) {               // + NF*NR*NS/2
        int gi = i - 6000;
        float4 acc = make_float4(0.f, 0.f, 0.f, 0.f);
        #pragma unroll 8
        for (int j = 0; j < NSPLIT; j++) {
            float4 p = Gp[(size_t)j * 16000 + gi];
            acc.x += p.x; acc.y += p.y; acc.z += p.z; acc.w += p.w;
        }
        ((float4*)g_G)[gi] = acc;
    }
}

// ---------------- kernel 4: mic partials FIRST, then s_A replicate -------
__global__ void k_out1(const float* __restrict__ T, float* __restrict__ out) {
    __shared__ float2 sV[NK][CH];
    int bx = blockIdx.x;
    int tid = threadIdx.x;

    if (bx < MICP_BLOCKS) {
        // ---- mic partials: block = (r, f, c); 50-iteration GEMV chunk ----
        int c = bx % MICCH;
        int t2 = bx / MICCH;
        int f = t2 % NF;
        int r = t2 / NF;
        int s0 = c * CH;
        for (int i = tid; i < NK * CH; i += 256) {
            int k = i / CH, s = i - k * CH;
            float2 a = g_A2[(f * NK + k) * NS + s0 + s];
            float2 g = g_G[(f * NR + r) * NS + s0 + s];
            sV[k][s] = make_float2(a.x * g.x - a.y * g.y, a.x * g.y + a.y * g.x);
        }
        __syncthreads();

        int b  = tid & (NB - 1);
        int kh = tid >> 7;
        float mre[3] = {0.f, 0.f, 0.f}, mim[3] = {0.f, 0.f, 0.f};
        #pragma unroll 5
        for (int s = 0; s < CH; s++) {
            float t = __ldg(&T[(size_t)(s0 + s) * NB + b]);
            #pragma unroll
            for (int j = 0; j < 3; j++) {
                float2 v = sV[kh * 3 + j][s];
                mre[j] = fmaf(v.x, t, mre[j]);
                mim[j] = fmaf(v.y, t, mim[j]);
            }
        }
        int rfk = (r * NF + f) * NK + kh * 3;
        #pragma unroll
        for (int j = 0; j < 3; j++)
            g_micp[((size_t)c * NRFK + rfk + j) * NB + b] = make_float2(mre[j], mim[j]);
        return;
    }

    // ---- s_A replicate: 4 items/thread, ALL loads issued before compute ----
    int base = (bx - MICP_BLOCKS) * 256 + tid;
    int ids[4];
    int rows[4], ss[4];
    float4 A01[4], A23[4], G01[4], G23[4];
    #pragma unroll
    for (int it = 0; it < 4; it++) {
        int id = base + it * REPA_STRIDE;
        ids[it] = id;
        int idc = (id < REPA_ITEMS) ? id : 0;
        int q = idc % 100;
        int row = idc / 100;
        int s = q * 4;
        rows[it] = row; ss[it] = s;
        int r = row / 360;
        int rem = row - r * 360;
        int f = rem / 72;
        int k = (rem - f * 72) % NK;
        const float4* a4 = (const float4*)&g_A2[(f * NK + k) * NS + s];
        const float4* g4 = (const float4*)&g_G[(f * NR + r) * NS + s];
        A01[it] = a4[0]; A23[it] = a4[1];
        G01[it] = g4[0]; G23[it] = g4[1];
    }
    #pragma unroll
    for (int it = 0; it < 4; it++) {
        if (ids[it] < REPA_ITEMS) {
            float4 a01 = A01[it], a23 = A23[it];
            float4 g01 = G01[it], g23 = G23[it];
            float4 re, im;
            re.x = a01.x * g01.x - a01.y * g01.y;  im.x = a01.x * g01.y + a01.y * g01.x;
            re.y = a01.z * g01.z - a01.w * g01.w;  im.y = a01.z * g01.w + a01.w * g01.z;
            re.z = a23.x * g23.x - a23.y * g23.y;  im.z = a23.x * g23.y + a23.y * g23.x;
            re.w = a23.z * g23.z - a23.w * g23.w;  im.w = a23.z * g23.w + a23.w * g23.z;
            *(float4*)&out[(size_t)rows[it] * NS + ss[it]] = re;
            *(float4*)&out[(size_t)(NROW + rows[it]) * NS + ss[it]] = im;
        }
    }
}

// ---------------- kernel 5: mic reduce + replicate ----------------
__global__ void k_micout(float* __restrict__ out) {
    int id = blockIdx.x * blockDim.x + threadIdx.x;
    if (id >= NROW * NB) return;
    int b = id & (NB - 1);
    int row = id >> 7;
    int r = row / 360;
    int rem = row - r * 360;
    int f = rem / 72;
    int k = (rem - f * 72) % NK;
    int rfk = (r * NF + f) * NK + k;
    float2 acc = make_float2(0.f, 0.f);
    #pragma unroll
    for (int c = 0; c < MICCH; c++) {
        float2 p = g_micp[((size_t)c * NRFK + rfk) * NB + b];
        acc.x += p.x; acc.y += p.y;
    }
    const size_t MICBASE = (size_t)2 * NROW * NS;
    out[MICBASE + (size_t)row * NB + b] = acc.x;
    out[MICBASE + (size_t)(NROW + row) * NB + b] = acc.y;
}

// ---------------- launcher ----------------
extern "C" void kernel_launch(void* const* d_in, const int* in_sizes, int n_in,
                              void* d_out, int out_size) {
    const float* T   = (const float*)d_in[0];
    const float* w   = (const float*)d_in[1];
    const float* th  = (const float*)d_in[2];
    const float* fv  = (const float*)d_in[3];
    const float* txp = (const float*)d_in[4];
    const float* rxp = (const float*)d_in[5];
    const float* mp  = (const float*)d_in[6];
    const float* sp  = (const float*)d_in[7];
    float* out = (float*)d_out;

    k_setup<<<MB_META + MB_C1 + MB_C2, 256>>>(w, th, fv, txp, rxp, mp);  // 1
    k_main<<<NF * NSPLIT, 224>>>(sp, fv);                                // 2
    k_reduce<<<172, 128>>>();                                            // 3
    k_out1<<<MICP_BLOCKS + REPA_BLOCKS, 256>>>(T, out);                  // 4 <- ncu
    k_micout<<<(NROW * NB + 255) / 256, 256>>>(out);                     // 5
}

// round 13
// speedup vs baseline: 1.1174x; 1.1174x over previous
#include <cuda_runtime.h>
#include <cstdint>

typedef unsigned long long ull;

#define NF 5
#define NK 6
#define NT 12
#define NR 16
#define NM 3600
#define NS 400
#define NSH 200            // 2 scenes per thread: (s, s+200)
#define NB 128
#define NSPLIT 120
#define MPW 30             // NM / NSPLIT (compile-time!)
#define NROW 5760          // Rx*F*72
#define NRFK 480           // Rx*F*6
#define MICCH 8
#define CH   (NS / MICCH)  // 50

// staged chunk: per m 12 float4 (C1:3, C2:8, meta:1)
#define NF4_C1   (MPW * 3)            // 90
#define NF4_C2   (MPW * 8)            // 240
#define NF4_TOT  (MPW * 12)           // 360
#define C2_BASE  NF4_C1               // 90
#define META_BASE (NF4_C1 + NF4_C2)   // 330

// merged setup kernel block ranges (256 threads each)
#define MB_META 15
#define MB_C1   141
#define MB_C2   282

// out1 grid: mic partial blocks FIRST, then batched repA blocks
#define MICP_BLOCKS (NR * NF * MICCH)   // 640
#define REPA_ITEMS  (NROW * 100)        // 576000 float4-pairs
#define REPA_BLOCKS 563                  // ceil(576000 / (256*4))
#define REPA_STRIDE (REPA_BLOCKS * 256)  // 144128

#define TWO_PI_D     6.283185307179586
#define INV2PI_F     0.15915494309189535f
#define PI2_HI_F     6.2831854820251465f
#define PI2_LO_F    -1.7484555e-7f
#define PI_F         3.14159265358979f
#define THETA_HI     0.3490658503988659f   // 20*pi/180

// ---------------- scratch (device globals; no allocation) ----------------
__device__ __align__(16) float g_C1f[NF * NM * 12];   // per (f,m): cr0..5, ci0..5
__device__ __align__(16) float g_C2f[NF * NM * 32];   // per (f,m): cr0..15, ci0..15
__device__ __align__(16) float4 g_meta4[NM];
__device__ __align__(16) float2 g_A2p[NSPLIT * NF * NK * NS];
__device__ __align__(16) float2 g_Gp [NSPLIT * NF * NR * NS];
__device__ __align__(16) float2 g_A2[NF * NK * NS];
__device__ __align__(16) float2 g_G [NF * NR * NS];
__device__ float2 g_micp[MICCH * NRFK * NB];

// ---------------- packed f32x2 helpers ----------------
__device__ __forceinline__ ull pk(float x, float y) {
    ull r; asm("mov.b64 %0, {%1, %2};" : "=l"(r) : "f"(x), "f"(y)); return r;
}
__device__ __forceinline__ float2 upk(ull v) {
    float x, y; asm("mov.b64 {%0, %1}, %2;" : "=f"(x), "=f"(y) : "l"(v));
    return make_float2(x, y);
}
__device__ __forceinline__ ull fma2(ull a, ull b, ull c) {
    ull d; asm("fma.rn.f32x2 %0, %1, %2, %3;" : "=l"(d) : "l"(a), "l"(b), "l"(c));
    return d;
}

// ---- fp32 angle reduction ----
__device__ __forceinline__ float reduce_ang(float kd_hi, float d) {
    float p = kd_hi * d;
    float n = rintf(p * INV2PI_F);
    float r1 = fmaf(-n, PI2_HI_F, p);
    r1 = fmaf(-n, PI2_LO_F, r1);
    return r1;
}

__device__ __forceinline__ void cexp_parts(float kd_hi, float d, float& a1, float& a2) {
    float amp = __fdividef(1e-3f, d * d);
    float sn, cs;
    __sincosf(reduce_ang(kd_hi, d), &sn, &cs);
    a1 = amp * cs; a2 = amp * sn;     // h = a1 - i*a2
}

__device__ __forceinline__ void cmac_s(float& ar, float& ai, float cr, float ci,
                                       float hr, float hi) {
    ar = fmaf(cr, hr, ar); ar = fmaf(-ci, hi, ar);
    ai = fmaf(cr, hi, ai); ai = fmaf(ci, hr, ai);
}

__device__ __forceinline__ float2 meta_phase(const float* theta_in, int m) {
    float th = theta_in[m];
    th = fminf(fmaxf(th, -PI_F), THETA_HI);
    float ps, pc; __sincosf(th, &ps, &pc);
    return make_float2(pc, ps);
}

// ---------------- kernel 1: merged setup (meta | C1 | C2) ----------------
__global__ void k_setup(const float* __restrict__ w,   const float* __restrict__ theta_in,
                        const float* __restrict__ fv,  const float* __restrict__ txp,
                        const float* __restrict__ rxp, const float* __restrict__ metap) {
    __shared__ float2 spri[NF * NK * NT];
    __shared__ float  sant[NR * 3];
    __shared__ float  sf[NF];
    int bx = blockIdx.x;
    int tid = threadIdx.x;

    if (bx < MB_META) {
        int m = bx * 256 + tid;
        if (m < NM)
            g_meta4[m] = make_float4(metap[3 * m + 0], metap[3 * m + 1], metap[3 * m + 2], 0.f);
        return;
    }

    if (bx < MB_META + MB_C1) {
        // ---- C1: 2 threads per (f,m), 3 k's each ----
        if (tid < NT * 3) sant[tid] = txp[tid];
        if (tid >= 64 && tid < 64 + NF) sf[tid - 64] = fv[tid - 64];
        for (int i = tid; i < NF * NK * NT; i += 256) {
            float s, c; sincosf(w[i], &s, &c);
            spri[i] = make_float2(c, s);
        }
        __syncthreads();

        int t = (bx - MB_META) * 256 + tid;
        if (t >= NF * NM * 2) return;
        int half = t & 1;
        int g = t >> 1;
        int fi = g / NM;
        int m  = g - fi * NM;

        float2 ph = meta_phase(theta_in, m);
        float mx = metap[3 * m + 0], my = metap[3 * m + 1], mz = metap[3 * m + 2];
        float kd_hi = (float)(TWO_PI_D * (double)sf[fi] / 3.0e8);

        float h1r[NT], h1i[NT];
        #pragma unroll
        for (int tx = 0; tx < NT; tx++) {
            float dx = sant[3 * tx + 0] - mx, dy = sant[3 * tx + 1] - my, dz = sant[3 * tx + 2] - mz;
            float d = sqrtf(dx * dx + dy * dy + dz * dz);
            float a1, a2; cexp_parts(kd_hi, d, a1, a2);
            h1r[tx] = a1; h1i[tx] = -a2;
        }
        float* dst = g_C1f + ((size_t)fi * NM + m) * 12;
        #pragma unroll
        for (int kk = 0; kk < 3; kk++) {
            int k = half * 3 + kk;
            float ar = 0.f, ai = 0.f;
            #pragma unroll
            for (int tx = 0; tx < NT; tx++) {
                float2 p = spri[(fi * NK + k) * NT + tx];
                cmac_s(ar, ai, p.x, p.y, h1r[tx], h1i[tx]);
            }
            dst[k]     = ar * ph.x - ai * ph.y;
            dst[6 + k] = ar * ph.y + ai * ph.x;
        }
        return;
    }

    // ---- C2: 4 threads per (f,m), 4 r's each ----
    if (tid < NR * 3) sant[tid] = rxp[tid];
    if (tid >= 64 && tid < 64 + NF) sf[tid - 64] = fv[tid - 64];
    __syncthreads();

    int t = (bx - MB_META - MB_C1) * 256 + tid;
    if (t >= NF * NM * 4) return;
    int rq = t & 3;
    int g = t >> 2;
    int fi = g / NM;
    int m  = g - fi * NM;

    float2 ph = meta_phase(theta_in, m);
    float mx = metap[3 * m + 0], my = metap[3 * m + 1], mz = metap[3 * m + 2];
    float kd_hi = (float)(TWO_PI_D * (double)sf[fi] / 3.0e8);

    float cr[4], ci[4];
    int r0 = rq * 4;
    #pragma unroll
    for (int j = 0; j < 4; j++) {
        int r = r0 + j;
        float dx = sant[3 * r + 0] - mx, dy = sant[3 * r + 1] - my, dz = sant[3 * r + 2] - mz;
        float d = sqrtf(dx * dx + dy * dy + dz * dz);
        float a1, a2; cexp_parts(kd_hi, d, a1, a2);
        float hr = a1, hi = -a2;
        cr[j] = ph.x * hr - ph.y * hi;
        ci[j] = ph.x * hi + ph.y * hr;
    }
    float* dst = g_C2f + ((size_t)fi * NM + m) * 32;
    ((float4*)dst)[rq]        = make_float4(cr[0], cr[1], cr[2], cr[3]);
    ((float4*)(dst + 16))[rq] = make_float4(ci[0], ci[1], ci[2], ci[3]);
}

// ---------------- kernel 2: fused A2 + G (fixed MPW=30, proven) ----------
__global__ void __launch_bounds__(224, 2) k_main(const float* __restrict__ scenep,
                                                 const float* __restrict__ fv) {
    __shared__ __align__(16) float4 sbuf[NF4_TOT];

    int tid = threadIdx.x;
    int item = blockIdx.x;               // 0..599
    int f  = item / NSPLIT;
    int ms = item - f * NSPLIT;
    int m0 = ms * MPW;

    {
        const float4* c1g = (const float4*)g_C1f + (size_t)f * NM * 3 + (size_t)m0 * 3;
        const float4* c2g = (const float4*)g_C2f + (size_t)f * NM * 8 + (size_t)m0 * 8;
        const float4* mg  = g_meta4 + m0;
        for (int j = tid; j < NF4_TOT; j += 224) {
            const float4* src;
            if (j < C2_BASE)        src = c1g + j;
            else if (j < META_BASE) src = c2g + (j - C2_BASE);
            else                    src = mg  + (j - META_BASE);
            unsigned sa32 = (unsigned)__cvta_generic_to_shared(&sbuf[j]);
            asm volatile("cp.async.cg.shared.global [%0], [%1], 16;"
                         :: "r"(sa32), "l"(src) : "memory");
        }
        asm volatile("cp.async.commit_group;" ::: "memory");
    }

    bool valid = (tid < NSH);
    int sa = valid ? tid : 0;
    int sb = sa + NSH;
    float sx1 = scenep[3 * sa + 0], sy1 = scenep[3 * sa + 1], sz1 = scenep[3 * sa + 2];
    float sx2 = scenep[3 * sb + 0], sy2 = scenep[3 * sb + 1], sz2 = scenep[3 * sb + 2];

    float kd_hi = (float)(TWO_PI_D * (double)__ldg(&fv[f]) / 3.0e8);

    ull aRa[3], aIa[3], gRa[8], gIa[8];
    ull aRb[3], aIb[3], gRb[8], gIb[8];
    #pragma unroll
    for (int i = 0; i < 3; i++) { aRa[i]=0ull; aIa[i]=0ull; aRb[i]=0ull; aIb[i]=0ull; }
    #pragma unroll
    for (int i = 0; i < 8; i++) { gRa[i]=0ull; gIa[i]=0ull; gRb[i]=0ull; gIb[i]=0ull; }

    asm volatile("cp.async.wait_group 0;" ::: "memory");
    __syncthreads();

    #pragma unroll 3
    for (int m = 0; m < MPW; ++m) {
        float4 mp = sbuf[META_BASE + m];

        float dx1 = mp.x - sx1, dy1 = mp.y - sy1, dz1 = mp.z - sz1;
        float d2a = fmaf(dx1, dx1, fmaf(dy1, dy1, dz1 * dz1));
        float rsa = rsqrtf(d2a);
        float da  = d2a * rsa;
        float ampa = 1e-3f * rsa * rsa;
        float sna, csa;
        __sincosf(reduce_ang(kd_hi, da), &sna, &csa);
        float hxa = ampa * csa, hya = -ampa * sna;
        ull hx2a  = pk(hxa, hxa);
        ull hy2a  = pk(hya, hya);
        ull hyn2a = pk(-hya, -hya);

        float dx2 = mp.x - sx2, dy2 = mp.y - sy2, dz2 = mp.z - sz2;
        float d2b = fmaf(dx2, dx2, fmaf(dy2, dy2, dz2 * dz2));
        float rsb = rsqrtf(d2b);
        float db  = d2b * rsb;
        float ampb = 1e-3f * rsb * rsb;
        float snb, csb;
        __sincosf(reduce_ang(kd_hi, db), &snb, &csb);
        float hxb = ampb * csb, hyb = -ampb * snb;
        ull hx2b  = pk(hxb, hxb);
        ull hy2b  = pk(hyb, hyb);
        ull hyn2b = pk(-hyb, -hyb);

        #define PMAC2(Ra, Ia, Rb, Ib, CR, CI)                  \
            Ra = fma2(CR, hx2a, Ra); Ra = fma2(CI, hyn2a, Ra); \
            Ia = fma2(CR, hy2a, Ia); Ia = fma2(CI, hx2a, Ia);  \
            Rb = fma2(CR, hx2b, Rb); Rb = fma2(CI, hyn2b, Rb); \
            Ib = fma2(CR, hy2b, Ib); Ib = fma2(CI, hx2b, Ib);

        {
            const ulonglong2* c1s = (const ulonglong2*)&sbuf[m * 3];
            ulonglong2 u0 = c1s[0];
            ulonglong2 u1 = c1s[1];
            ulonglong2 u2 = c1s[2];
            PMAC2(aRa[0], aIa[0], aRb[0], aIb[0], u0.x, u1.y)
            PMAC2(aRa[1], aIa[1], aRb[1], aIb[1], u0.y, u2.x)
            PMAC2(aRa[2], aIa[2], aRb[2], aIb[2], u1.x, u2.y)
        }
        {
            const ulonglong2* c2s = (const ulonglong2*)&sbuf[C2_BASE + m * 8];
            ulonglong2 v0 = c2s[0];
            ulonglong2 v1 = c2s[1];
            ulonglong2 v2 = c2s[2];
            ulonglong2 v3 = c2s[3];
            ulonglong2 w0 = c2s[4];
            ulonglong2 w1 = c2s[5];
            ulonglong2 w2 = c2s[6];
            ulonglong2 w3 = c2s[7];
            PMAC2(gRa[0], gIa[0], gRb[0], gIb[0], v0.x, w0.x)
            PMAC2(gRa[1], gIa[1], gRb[1], gIb[1], v0.y, w0.y)
            PMAC2(gRa[2], gIa[2], gRb[2], gIb[2], v1.x, w1.x)
            PMAC2(gRa[3], gIa[3], gRb[3], gIb[3], v1.y, w1.y)
            PMAC2(gRa[4], gIa[4], gRb[4], gIb[4], v2.x, w2.x)
            PMAC2(gRa[5], gIa[5], gRb[5], gIb[5], v2.y, w2.y)
            PMAC2(gRa[6], gIa[6], gRb[6], gIb[6], v3.x, w3.x)
            PMAC2(gRa[7], gIa[7], gRb[7], gIb[7], v3.y, w3.y)
        }
        #undef PMAC2
    }

    if (valid) {
        float2* A2p = g_A2p + (size_t)ms * (NF * NK * NS);
        #pragma unroll
        for (int j = 0; j < 3; j++) {
            float2 r1 = upk(aRa[j]), i1 = upk(aIa[j]);
            float2 r2 = upk(aRb[j]), i2 = upk(aIb[j]);
            A2p[(f * NK + 2 * j)     * NS + sa] = make_float2(r1.x, i1.x);
            A2p[(f * NK + 2 * j + 1) * NS + sa] = make_float2(r1.y, i1.y);
            A2p[(f * NK + 2 * j)     * NS + sb] = make_float2(r2.x, i2.x);
            A2p[(f * NK + 2 * j + 1) * NS + sb] = make_float2(r2.y, i2.y);
        }
        float2* Gp = g_Gp + (size_t)ms * (NF * NR * NS);
        #pragma unroll
        for (int j = 0; j < 8; j++) {
            float2 r1 = upk(gRa[j]), i1 = upk(gIa[j]);
            float2 r2 = upk(gRb[j]), i2 = upk(gIb[j]);
            Gp[(f * NR + 2 * j)     * NS + sa] = make_float2(r1.x, i1.x);
            Gp[(f * NR + 2 * j + 1) * NS + sa] = make_float2(r1.y, i1.y);
            Gp[(f * NR + 2 * j)     * NS + sb] = make_float2(r2.x, i2.x);
            Gp[(f * NR + 2 * j + 1) * NS + sb] = make_float2(r2.y, i2.y);
        }
    }
}

// ---------------- kernel 3: reduce partials (128 thr, 172 blocks) --------
__global__ void __launch_bounds__(128) k_reduce() {
    int i = blockIdx.x * 128 + threadIdx.x;
    const float4* Ap = (const float4*)g_A2p;
    const float4* Gp = (const float4*)g_Gp;
    if (i < 6000) {                       // NF*NK*NS/2
        float4 acc = make_float4(0.f, 0.f, 0.f, 0.f);
        #pragma unroll 10
        for (int j = 0; j < NSPLIT; j++) {
            float4 p = Ap[(size_t)j * 6000 + i];
            acc.x += p.x; acc.y += p.y; acc.z += p.z; acc.w += p.w;
        }
        ((float4*)g_A2)[i] = acc;
    } else if (i < 22000) {               // + NF*NR*NS/2
        int gi = i - 6000;
        float4 acc = make_float4(0.f, 0.f, 0.f, 0.f);
        #pragma unroll 10
        for (int j = 0; j < NSPLIT; j++) {
            float4 p = Gp[(size_t)j * 16000 + gi];
            acc.x += p.x; acc.y += p.y; acc.z += p.z; acc.w += p.w;
        }
        ((float4*)g_G)[gi] = acc;
    }
}

// ---------------- kernel 4: mic partials FIRST, then batched s_A ---------
__global__ void k_out1(const float* __restrict__ T, float* __restrict__ out) {
    __shared__ float2 sV[NK][CH];
    int bx = blockIdx.x;
    int tid = threadIdx.x;

    if (bx < MICP_BLOCKS) {
        // ---- mic partials: block = (r, f, c); 50-iteration GEMV chunk ----
        int c = bx % MICCH;
        int t2 = bx / MICCH;
        int f = t2 % NF;
        int r = t2 / NF;
        int s0 = c * CH;
        for (int i = tid; i < NK * CH; i += 256) {
            int k = i / CH, s = i - k * CH;
            float2 a = g_A2[(f * NK + k) * NS + s0 + s];
            float2 g = g_G[(f * NR + r) * NS + s0 + s];
            sV[k][s] = make_float2(a.x * g.x - a.y * g.y, a.x * g.y + a.y * g.x);
        }
        __syncthreads();

        int b  = tid & (NB - 1);
        int kh = tid >> 7;
        float mre[3] = {0.f, 0.f, 0.f}, mim[3] = {0.f, 0.f, 0.f};
        #pragma unroll 5
        for (int s = 0; s < CH; s++) {
            float t = __ldg(&T[(size_t)(s0 + s) * NB + b]);
            #pragma unroll
            for (int j = 0; j < 3; j++) {
                float2 v = sV[kh * 3 + j][s];
                mre[j] = fmaf(v.x, t, mre[j]);
                mim[j] = fmaf(v.y, t, mim[j]);
            }
        }
        int rfk = (r * NF + f) * NK + kh * 3;
        #pragma unroll
        for (int j = 0; j < 3; j++)
            g_micp[((size_t)c * NRFK + rfk + j) * NB + b] = make_float2(mre[j], mim[j]);
        return;
    }

    // ---- s_A replicate: 4 items/thread, ALL loads issued before compute ----
    int base = (bx - MICP_BLOCKS) * 256 + tid;
    int ids[4];
    int rows[4], ss[4];
    float4 A01[4], A23[4], G01[4], G23[4];
    #pragma unroll
    for (int it = 0; it < 4; it++) {
        int id = base + it * REPA_STRIDE;
        ids[it] = id;
        int idc = (id < REPA_ITEMS) ? id : 0;
        int q = idc % 100;
        int row = idc / 100;
        int s = q * 4;
        rows[it] = row; ss[it] = s;
        int r = row / 360;
        int rem = row - r * 360;
        int f = rem / 72;
        int k = (rem - f * 72) % NK;
        const float4* a4 = (const float4*)&g_A2[(f * NK + k) * NS + s];
        const float4* g4 = (const float4*)&g_G[(f * NR + r) * NS + s];
        A01[it] = a4[0]; A23[it] = a4[1];
        G01[it] = g4[0]; G23[it] = g4[1];
    }
    #pragma unroll
    for (int it = 0; it < 4; it++) {
        if (ids[it] < REPA_ITEMS) {
            float4 a01 = A01[it], a23 = A23[it];
            float4 g01 = G01[it], g23 = G23[it];
            float4 re, im;
            re.x = a01.x * g01.x - a01.y * g01.y;  im.x = a01.x * g01.y + a01.y * g01.x;
            re.y = a01.z * g01.z - a01.w * g01.w;  im.y = a01.z * g01.w + a01.w * g01.z;
            re.z = a23.x * g23.x - a23.y * g23.y;  im.z = a23.x * g23.y + a23.y * g23.x;
            re.w = a23.z * g23.z - a23.w * g23.w;  im.w = a23.z * g23.w + a23.w * g23.z;
            *(float4*)&out[(size_t)rows[it] * NS + ss[it]] = re;
            *(float4*)&out[(size_t)(NROW + rows[it]) * NS + ss[it]] = im;
        }
    }
}

// ---------------- kernel 5: mic reduce + replicate ----------------
__global__ void k_micout(float* __restrict__ out) {
    int id = blockIdx.x * blockDim.x + threadIdx.x;
    if (id >= NROW * NB) return;
    int b = id & (NB - 1);
    int row = id >> 7;
    int r = row / 360;
    int rem = row - r * 360;
    int f = rem / 72;
    int k = (rem - f * 72) % NK;
    int rfk = (r * NF + f) * NK + k;
    float2 acc = make_float2(0.f, 0.f);
    #pragma unroll
    for (int c = 0; c < MICCH; c++) {
        float2 p = g_micp[((size_t)c * NRFK + rfk) * NB + b];
        acc.x += p.x; acc.y += p.y;
    }
    const size_t MICBASE = (size_t)2 * NROW * NS;
    out[MICBASE + (size_t)row * NB + b] = acc.x;
    out[MICBASE + (size_t)(NROW + row) * NB + b] = acc.y;
}

// ---------------- launcher ----------------
extern "C" void kernel_launch(void* const* d_in, const int* in_sizes, int n_in,
                              void* d_out, int out_size) {
    const float* T   = (const float*)d_in[0];
    const float* w   = (const float*)d_in[1];
    const float* th  = (const float*)d_in[2];
    const float* fv  = (const float*)d_in[3];
    const float* txp = (const float*)d_in[4];
    const float* rxp = (const float*)d_in[5];
    const float* mp  = (const float*)d_in[6];
    const float* sp  = (const float*)d_in[7];
    float* out = (float*)d_out;

    k_setup<<<MB_META + MB_C1 + MB_C2, 256>>>(w, th, fv, txp, rxp, mp);  // 1
    k_main<<<NF * NSPLIT, 224>>>(sp, fv);                                // 2
    k_reduce<<<172, 128>>>();                                            // 3
    k_out1<<<MICP_BLOCKS + REPA_BLOCKS, 256>>>(T, out);                  // 4 <- ncu
    k_micout<<<(NROW * NB + 255) / 256, 256>>>(out);                     // 5
}